// round 5
// baseline (speedup 1.0000x reference)
#include <cuda_runtime.h>
#include <math.h>

#define B_   8
#define L_   2048
#define D_   512
#define Y_   8921
#define ROWS_ (B_ * Y_)          // 71368

// Scratch for deterministic loss reduction (no device allocation allowed).
__device__ float g_partials[Y_];  // 8921 blocks in head kernel

// ---------------------------------------------------------------------------
// GEMM 1: scores[b,y,l] = sum_d U[y,d] * x[b,l,d]
// A = U [Y,D] row-major (k=d contiguous), B = x[b] [L,D] row-major (k=d contiguous)
// C tile 128(y) x 128(l), K-step 16, 256 threads, 8x8 per thread.
// ---------------------------------------------------------------------------
__global__ __launch_bounds__(256) void gemm_scores(
    const float* __restrict__ U, const float* __restrict__ X,
    float* __restrict__ S /* alpha buffer, scores out */)
{
    __shared__ float As[128][17];   // [m(y)][k] (+1 pad: conflict-free compute loads)
    __shared__ float Bs[16][128];   // [k][n(l)] transposed for vector compute loads

    const int b  = blockIdx.z;
    const int y0 = blockIdx.y * 128;
    const int l0 = blockIdx.x * 128;
    const int tid = threadIdx.x;
    const int ty = tid >> 4;        // 0..15 -> y
    const int tx = tid & 15;        // 0..15 -> l

    const float* xb = X + (size_t)b * (L_ * D_) + (size_t)l0 * D_;

    float acc[8][8];
#pragma unroll
    for (int i = 0; i < 8; i++)
#pragma unroll
        for (int j = 0; j < 8; j++) acc[i][j] = 0.f;

    for (int kb = 0; kb < D_; kb += 16) {
        // --- load A (U) tile: 128 rows x 16 k, scalar, coalesced 16/row ---
#pragma unroll
        for (int i = 0; i < 8; i++) {
            int f = tid + i * 256;          // 0..2047
            int row = f >> 4;               // y within tile
            int col = f & 15;               // k
            int gy = y0 + row;
            As[row][col] = (gy < Y_) ? U[(size_t)gy * D_ + kb + col] : 0.f;
        }
        // --- load B (x) tile: 128 l x 16 d, float4 global, transposed store ---
#pragma unroll
        for (int i = 0; i < 2; i++) {
            int f = tid + i * 256;          // 0..511 (float4s)
            int row = f >> 2;               // l within tile
            int c4  = (f & 3) * 4;          // k
            float4 v = *reinterpret_cast<const float4*>(xb + (size_t)row * D_ + kb + c4);
            Bs[c4 + 0][row] = v.x;
            Bs[c4 + 1][row] = v.y;
            Bs[c4 + 2][row] = v.z;
            Bs[c4 + 3][row] = v.w;
        }
        __syncthreads();

#pragma unroll
        for (int k = 0; k < 16; k++) {
            float a[8];
#pragma unroll
            for (int i = 0; i < 8; i++) a[i] = As[ty * 8 + i][k];
            float4 b0 = *reinterpret_cast<const float4*>(&Bs[k][tx * 8]);
            float4 b1 = *reinterpret_cast<const float4*>(&Bs[k][tx * 8 + 4]);
            float bb[8] = {b0.x, b0.y, b0.z, b0.w, b1.x, b1.y, b1.z, b1.w};
#pragma unroll
            for (int i = 0; i < 8; i++)
#pragma unroll
                for (int j = 0; j < 8; j++)
                    acc[i][j] = fmaf(a[i], bb[j], acc[i][j]);
        }
        __syncthreads();
    }

    // --- store scores (alpha buffer is only 4B-aligned: scalar stores) ---
#pragma unroll
    for (int i = 0; i < 8; i++) {
        int gy = y0 + ty * 8 + i;
        if (gy < Y_) {
            float* out = S + ((size_t)b * Y_ + gy) * L_ + l0 + tx * 8;
#pragma unroll
            for (int j = 0; j < 8; j++) out[j] = acc[i][j];
        }
    }
}

// ---------------------------------------------------------------------------
// Row softmax over L=2048, in place on the alpha buffer. One block per row.
// ---------------------------------------------------------------------------
__global__ __launch_bounds__(256) void softmax_rows(float* __restrict__ S)
{
    const int r = blockIdx.x;                       // 0..71367
    float* p = S + (size_t)r * L_;
    const int t = threadIdx.x;

    float v[8];
    float mx = -3.402823466e38f;
#pragma unroll
    for (int j = 0; j < 8; j++) {
        v[j] = p[t + j * 256];
        mx = fmaxf(mx, v[j]);
    }

    __shared__ float sm[8];
#pragma unroll
    for (int o = 16; o; o >>= 1) mx = fmaxf(mx, __shfl_xor_sync(0xffffffffu, mx, o));
    if ((t & 31) == 0) sm[t >> 5] = mx;
    __syncthreads();
    mx = sm[0];
#pragma unroll
    for (int i = 1; i < 8; i++) mx = fmaxf(mx, sm[i]);
    __syncthreads();   // before reusing sm for the sum

    float sum = 0.f;
#pragma unroll
    for (int j = 0; j < 8; j++) {
        v[j] = expf(v[j] - mx);
        sum += v[j];
    }
#pragma unroll
    for (int o = 16; o; o >>= 1) sum += __shfl_xor_sync(0xffffffffu, sum, o);
    if ((t & 31) == 0) sm[t >> 5] = sum;
    __syncthreads();
    sum = 0.f;
#pragma unroll
    for (int i = 0; i < 8; i++) sum += sm[i];
    float inv = 1.f / sum;

#pragma unroll
    for (int j = 0; j < 8; j++) p[t + j * 256] = v[j] * inv;
}

// ---------------------------------------------------------------------------
// GEMM 2: m[b,y,d] = sum_l alpha[b,y,l] * x[b,l,d]
// A = alpha [Y,L] row-major (k=l contiguous, 4B-aligned only -> scalar loads)
// B = x[b] [L,D] row-major: Bs needs NO transpose (k=l is the row dim).
// ---------------------------------------------------------------------------
__global__ __launch_bounds__(256) void gemm_m(
    const float* __restrict__ A /* alpha */, const float* __restrict__ X,
    float* __restrict__ Mo)
{
    __shared__ float As[128][17];   // [m(y)][k(l)]
    __shared__ float Bs[16][128];   // [k(l)][n(d)]

    const int b  = blockIdx.z;
    const int y0 = blockIdx.y * 128;
    const int n0 = blockIdx.x * 128;
    const int tid = threadIdx.x;
    const int ty = tid >> 4;
    const int tx = tid & 15;

    const float* xb = X + (size_t)b * (L_ * D_);

    float acc[8][8];
#pragma unroll
    for (int i = 0; i < 8; i++)
#pragma unroll
        for (int j = 0; j < 8; j++) acc[i][j] = 0.f;

    for (int kb = 0; kb < L_; kb += 16) {
        // --- A (alpha) tile: scalar loads (misaligned base), coalesced 16/row ---
#pragma unroll
        for (int i = 0; i < 8; i++) {
            int f = tid + i * 256;
            int row = f >> 4;               // y
            int col = f & 15;               // l
            int gy = y0 + row;
            As[row][col] = (gy < Y_) ? A[((size_t)b * Y_ + gy) * L_ + kb + col] : 0.f;
        }
        // --- B (x) tile: direct layout, float4 ---
#pragma unroll
        for (int i = 0; i < 2; i++) {
            int f = tid + i * 256;          // 0..511 float4s  (16 rows * 32 f4/row)
            int row = f >> 5;               // l (k) 0..15
            int c4  = (f & 31) * 4;         // d
            *reinterpret_cast<float4*>(&Bs[row][c4]) =
                *reinterpret_cast<const float4*>(xb + (size_t)(kb + row) * D_ + n0 + c4);
        }
        __syncthreads();

#pragma unroll
        for (int k = 0; k < 16; k++) {
            float a[8];
#pragma unroll
            for (int i = 0; i < 8; i++) a[i] = As[ty * 8 + i][k];
            float4 b0 = *reinterpret_cast<const float4*>(&Bs[k][tx * 8]);
            float4 b1 = *reinterpret_cast<const float4*>(&Bs[k][tx * 8 + 4]);
            float bb[8] = {b0.x, b0.y, b0.z, b0.w, b1.x, b1.y, b1.z, b1.w};
#pragma unroll
            for (int i = 0; i < 8; i++)
#pragma unroll
                for (int j = 0; j < 8; j++)
                    acc[i][j] = fmaf(a[i], bb[j], acc[i][j]);
        }
        __syncthreads();
    }

#pragma unroll
    for (int i = 0; i < 8; i++) {
        int gy = y0 + ty * 8 + i;
        if (gy < Y_) {
            float* out = Mo + ((size_t)b * Y_ + gy) * D_ + n0 + tx * 8;
#pragma unroll
            for (int j = 0; j < 8; j++) out[j] = acc[i][j];
        }
    }
}

// ---------------------------------------------------------------------------
// Head: y[g] = dot(final_weight[yy,:], m[g,:]) + bias[yy];  per-block loss partials.
// One warp per row; 8 rows per block; grid = 8921 (71368 rows exactly).
// ---------------------------------------------------------------------------
__global__ __launch_bounds__(256) void head_kernel(
    const float* __restrict__ Mo, const float* __restrict__ FW,
    const float* __restrict__ bias, const float* __restrict__ target,
    float* __restrict__ Yout)
{
    const int w    = threadIdx.x >> 5;
    const int lane = threadIdx.x & 31;
    const int g    = blockIdx.x * 8 + w;        // row 0..71367
    const int yy   = g % Y_;

    const float* mr = Mo + (size_t)g * D_;      // 4B-aligned only -> scalar
    const float* fr = FW + (size_t)yy * D_;

    float s = 0.f;
#pragma unroll
    for (int j = 0; j < 16; j++)
        s = fmaf(mr[lane + j * 32], fr[lane + j * 32], s);
#pragma unroll
    for (int o = 16; o; o >>= 1) s += __shfl_xor_sync(0xffffffffu, s, o);

    __shared__ float sm[8];
    if (lane == 0) {
        float yv = s + bias[yy];
        Yout[g] = yv;
        float t = target[g];
        sm[w] = fmaxf(yv, 0.f) - yv * t + log1pf(expf(-fabsf(yv)));
    }
    __syncthreads();
    if (threadIdx.x == 0) {
        float acc = 0.f;
#pragma unroll
        for (int i = 0; i < 8; i++) acc += sm[i];
        g_partials[blockIdx.x] = acc;
    }
}

// ---------------------------------------------------------------------------
// Final deterministic loss reduction (1 block).
// ---------------------------------------------------------------------------
__global__ __launch_bounds__(1024) void loss_reduce(float* __restrict__ out)
{
    __shared__ double sm[32];
    double s = 0.0;
    for (int i = threadIdx.x; i < Y_; i += 1024) s += (double)g_partials[i];
#pragma unroll
    for (int o = 16; o; o >>= 1) s += __shfl_xor_sync(0xffffffffu, s, o);
    if ((threadIdx.x & 31) == 0) sm[threadIdx.x >> 5] = s;
    __syncthreads();
    if (threadIdx.x == 0) {
        double acc = 0.0;
#pragma unroll
        for (int i = 0; i < 32; i++) acc += sm[i];
        out[0] = (float)(acc / (double)ROWS_);
    }
}

// ---------------------------------------------------------------------------
// Launch. Inputs (metadata order): x, target, text_inputs(unused), U_weight,
// final_weight, final_bias. Output tuple: (y, loss, alpha, m) flattened.
// ---------------------------------------------------------------------------
extern "C" void kernel_launch(void* const* d_in, const int* in_sizes, int n_in,
                              void* d_out, int out_size)
{
    const float* x      = (const float*)d_in[0];
    const float* target = (const float*)d_in[1];
    // d_in[2] = text_inputs (int64) — unused by the reference math
    const float* U      = (const float*)d_in[3];
    const float* FW     = (const float*)d_in[4];
    const float* bias   = (const float*)d_in[5];

    float* out       = (float*)d_out;
    float* out_y     = out;                                         // [B,Y]
    float* out_loss  = out + (size_t)ROWS_;                          // [1]
    float* out_alpha = out + (size_t)ROWS_ + 1;                      // [B,Y,L]
    float* out_m     = out_alpha + (size_t)B_ * Y_ * L_;             // [B,Y,D]

    dim3 g1(L_ / 128, (Y_ + 127) / 128, B_);   // (16, 70, 8)
    gemm_scores<<<g1, 256>>>(U, x, out_alpha);

    softmax_rows<<<ROWS_, 256>>>(out_alpha);

    dim3 g2(D_ / 128, (Y_ + 127) / 128, B_);   // (4, 70, 8)
    gemm_m<<<g2, 256>>>(out_alpha, x, out_m);

    head_kernel<<<Y_, 256>>>(out_m, FW, bias, target, out_y);
    loss_reduce<<<1, 1024>>>(out_loss);
}